// round 16
// baseline (speedup 1.0000x reference)
#include <cuda_runtime.h>
#include <cuda_fp16.h>
#include <cstdint>
#include <math.h>

#define T 4096
#define H 1024
#define F 512
#define E 16
#define K 4
#define S (T*K)
#define SP ((size_t)E * T)          // padded slot space (per-expert regions)

// ---------------- scratch (device globals; no runtime allocation) ----------
__device__ int    g_counts[E];      // zero-init at load; re-zeroed by combine
__device__ int    g_slot_token[SP];
__device__ float  g_slot_w[SP];
__device__ int    g_token_slot[S];
// fp16 (RN) operands / activations / outputs
__device__ __align__(256) __half g_xh [(size_t)T * H];
__device__ __align__(256) __half g_w1h[(size_t)E * F * H];
__device__ __align__(256) __half g_w3h[(size_t)E * F * H];
__device__ __align__(256) __half g_w2h[(size_t)E * H * F];
__device__ __align__(256) __half g_hh [SP * F];
__device__ __align__(256) __half g_yh [SP * H];

// ---------------- helpers ---------------------------------------------------
__device__ __forceinline__ void mma16(float* d, const uint32_t* a,
                                      uint32_t b0, uint32_t b1) {
    asm volatile(
        "mma.sync.aligned.m16n8k16.row.col.f32.f16.f16.f32 "
        "{%0,%1,%2,%3}, {%4,%5,%6,%7}, {%8,%9}, {%0,%1,%2,%3};"
        : "+f"(d[0]), "+f"(d[1]), "+f"(d[2]), "+f"(d[3])
        : "r"(a[0]), "r"(a[1]), "r"(a[2]), "r"(a[3]), "r"(b0), "r"(b1));
}
__device__ __forceinline__ void ldsm4(uint32_t* r, uint32_t addr) {
    asm volatile(
        "ldmatrix.sync.aligned.m8n8.x4.shared.b16 {%0,%1,%2,%3}, [%4];"
        : "=r"(r[0]), "=r"(r[1]), "=r"(r[2]), "=r"(r[3]) : "r"(addr));
}
__device__ __forceinline__ uint32_t smem_u32(const void* p) {
    uint32_t a;
    asm("{ .reg .u64 t; cvta.to.shared.u64 t, %1; cvt.u32.u64 %0, t; }"
        : "=r"(a) : "l"(p));
    return a;
}
__device__ __forceinline__ void cp_async16(uint32_t dst, const void* src) {
    asm volatile("cp.async.cg.shared.global [%0], [%1], 16;" :: "r"(dst), "l"(src));
}
#define CP_COMMIT() asm volatile("cp.async.commit_group;" ::: "memory")
#define CP_WAIT2()  asm volatile("cp.async.wait_group 2;" ::: "memory")

// 128B-row SW128 swizzle (Swizzle<3,4,3>): XOR row bits [0:3) into 16B-col
// bits [4:7). ks chunk offsets {0,32,64,96} -> addr(ks) == addr(0) ^ (ks*32).
#define SWB128(b) ((b) ^ (((((uint32_t)(b)) >> 7) & 7) << 4))

#define BK 64
#define STG1B 49152     // gemm1: x 16KB + w1 16KB + w3 16KB (128B rows)
#define STG2B 49152     // gemm2: h 16KB + w2 32KB

// ---------------------------------------------------------------------------
// fp32x8 -> fp16x8 (RN)
// ---------------------------------------------------------------------------
__device__ __forceinline__ uint4 cvt8(float4 f0, float4 f1) {
    __half2 h0 = __floats2half2_rn(f0.x, f0.y), h1 = __floats2half2_rn(f0.z, f0.w);
    __half2 h2 = __floats2half2_rn(f1.x, f1.y), h3 = __floats2half2_rn(f1.z, f1.w);
    uint4 o;
    o.x = *(uint32_t*)&h0; o.y = *(uint32_t*)&h1;
    o.z = *(uint32_t*)&h2; o.w = *(uint32_t*)&h3;
    return o;
}
__device__ __forceinline__ void conv8(const float4* __restrict__ src,
                                      uint4* __restrict__ dst, size_t i) {
    dst[i] = cvt8(src[2 * i], src[2 * i + 1]);
}

// ---------------------------------------------------------------------------
// 0. fused prep + router
//    blocks [0, RB): router (exact fp32, float4-vectorized) + fp16 x emit
//    blocks [RB, RB+PB): w1 & w3 conversion, 4 LDG.128 in flight per iter
// ---------------------------------------------------------------------------
#define RB 512
#define PB 1536

__global__ void prep_router_kernel(const float* __restrict__ x,
                                   const float* __restrict__ gw,
                                   const float* __restrict__ bias,
                                   const float4* __restrict__ w1,
                                   const float4* __restrict__ w3) {
    if (blockIdx.x >= RB) {
        size_t i0 = (size_t)(blockIdx.x - RB) * blockDim.x + threadIdx.x;
        size_t stride = (size_t)PB * blockDim.x;
        const size_t nw = (size_t)E * F * H / 8;
        for (size_t i = i0; i < nw; i += stride) {
            // batch ALL loads before any convert/store -> 4 LDGs in flight
            float4 a0 = w1[2 * i], a1 = w1[2 * i + 1];
            float4 b0 = w3[2 * i], b1 = w3[2 * i + 1];
            ((uint4*)g_w1h)[i] = cvt8(a0, a1);
            ((uint4*)g_w3h)[i] = cvt8(b0, b1);
        }
        return;
    }
    // ---- router: one warp per token; float4 loads, coalesced fp16 stores ----
    int warp = (blockIdx.x * blockDim.x + threadIdx.x) >> 5;
    int lane = threadIdx.x & 31;
    if (warp >= T) return;

    const float4* xr4 = (const float4*)(x + (size_t)warp * H);
    __half2* xo2 = (__half2*)(g_xh + (size_t)warp * H);
    float acc[E];
#pragma unroll
    for (int e = 0; e < E; e++) acc[e] = 0.f;
#pragma unroll
    for (int it = 0; it < H / 128; it++) {       // 8 iters, 4 floats/lane
        int h4 = it * 32 + lane;
        float4 xv = xr4[h4];
        xo2[h4 * 2 + 0] = __floats2half2_rn(xv.x, xv.y);
        xo2[h4 * 2 + 1] = __floats2half2_rn(xv.z, xv.w);
#pragma unroll
        for (int e = 0; e < E; e++) {
            float4 g = __ldg((const float4*)(gw + e * H) + h4);
            acc[e] = fmaf(xv.x, g.x, fmaf(xv.y, g.y,
                     fmaf(xv.z, g.z, fmaf(xv.w, g.w, acc[e]))));
        }
    }
#pragma unroll
    for (int o = 16; o > 0; o >>= 1)
#pragma unroll
        for (int e = 0; e < E; e++)
            acc[e] += __shfl_xor_sync(0xffffffffu, acc[e], o);

    if (lane == 0) {
        float sc[E], sel[E];
#pragma unroll
        for (int e = 0; e < E; e++) {
            sc[e]  = 1.f / (1.f + expf(-acc[e]));
            sel[e] = sc[e] + bias[e];
        }
        bool used[E];
#pragma unroll
        for (int e = 0; e < E; e++) used[e] = false;
        float sum = 0.f;
        int   idx[K]; float w[K];
#pragma unroll
        for (int k = 0; k < K; k++) {
            float best = -1e30f; int bi = 0;
            for (int e = 0; e < E; e++)
                if (!used[e] && sel[e] > best) { best = sel[e]; bi = e; }
            used[bi] = true; idx[k] = bi; w[k] = sc[bi]; sum += sc[bi];
        }
        float inv = 1.f / sum;
#pragma unroll
        for (int k = 0; k < K; k++) {
            int e   = idx[k];
            int pos = e * T + atomicAdd(&g_counts[e], 1);
            g_slot_token[pos]        = warp;
            g_slot_w[pos]            = w[k] * inv;
            g_token_slot[warp*K + k] = pos;
        }
    }
}

// ---------------------------------------------------------------------------
// ldmatrix address offsets (region-relative, 128B rows; ks -> XOR ks*32)
// ---------------------------------------------------------------------------
__device__ __forceinline__ uint32_t a_off128(int r0, int lane) {
    int row = r0 + ((lane >> 3) & 1) * 8 + (lane & 7);
    return SWB128((uint32_t)(row * 128 + (lane >> 4) * 16));
}
__device__ __forceinline__ uint32_t b_off128(int c0, int lane) {
    int row = c0 + ((lane >> 4) << 3) + (lane & 7);
    return SWB128((uint32_t)(row * 128 + ((lane >> 3) & 1) * 16));
}

// ---------------------------------------------------------------------------
// 1. gemm1: h = silu(X@W1^T) * (X@W3^T)
//    CTA 128x128, 512 thr, warps 4Mx4N, BK=64, 4-stage cp.async.
//    Grid (x=expert[+1], y=n-tile, z=m-tile); x==E converts w2.
// ---------------------------------------------------------------------------
__global__ __launch_bounds__(512, 1) void gemm1_tc(const float4* __restrict__ w2) {
    if (blockIdx.x == E) {
        size_t i0 = (size_t)(blockIdx.z * gridDim.y + blockIdx.y) * blockDim.x
                  + threadIdx.x;
        size_t stride = (size_t)gridDim.z * gridDim.y * blockDim.x;
        const size_t nw = (size_t)E * H * F / 8;
        for (size_t i = i0; i < nw; i += stride) conv8(w2, (uint4*)g_w2h, i);
        return;
    }
    int e     = blockIdx.x;
    int off   = e * T;
    int count = g_counts[e];
    int m0    = blockIdx.z * 128;
    if (m0 >= count) return;
    int n0 = blockIdx.y * 128;

    extern __shared__ __half smh[];
    __shared__ int toks[128];

    int tid = threadIdx.x, wid = tid >> 5, lane = tid & 31;
    int q = lane >> 2, tq = lane & 3;
    int wM = wid & 3, wN = wid >> 2;        // 4 x 4 warps

    if (tid < 128) toks[tid] = g_slot_token[off + min(m0 + tid, count - 1)];
    __syncthreads();

    const __half* w1e = g_w1h + ((size_t)e * F + n0) * H;
    const __half* w3e = g_w3h + ((size_t)e * F + n0) * H;

    uint32_t sb0 = smem_u32(smh);
    int lrow = tid >> 2, lseg = tid & 3;     // 128 rows; segs {lseg, lseg+4}
    uint32_t wd0 = SWB128((uint32_t)(lrow * 128 + lseg * 16));
    uint32_t wd1 = SWB128((uint32_t)(lrow * 128 + (lseg + 4) * 16));

    uint32_t aOf[2], b1Of[2], b3Of[2];
#pragma unroll
    for (int mt = 0; mt < 2; mt++) aOf[mt] = a_off128(wM * 32 + mt * 16, lane);
#pragma unroll
    for (int p = 0; p < 2; p++) {
        b1Of[p] = 16384 + b_off128(wN * 32 + p * 16, lane);
        b3Of[p] = 32768 + b_off128(wN * 32 + p * 16, lane);
    }

    auto load_stage = [&](int kt, int buf) {
        uint32_t sb = sb0 + (uint32_t)buf * STG1B;
        int kf0 = kt * BK + lseg * 8;
        int kf1 = kf0 + 32;
        const __half* xrow = g_xh + (size_t)toks[lrow] * H;
        cp_async16(sb + wd0,         xrow + kf0);
        cp_async16(sb + wd1,         xrow + kf1);
        cp_async16(sb + 16384 + wd0, w1e + (size_t)lrow * H + kf0);
        cp_async16(sb + 16384 + wd1, w1e + (size_t)lrow * H + kf1);
        cp_async16(sb + 32768 + wd0, w3e + (size_t)lrow * H + kf0);
        cp_async16(sb + 32768 + wd1, w3e + (size_t)lrow * H + kf1);
    };

    float acc1[2][4][4] = {}, acc3[2][4][4] = {};

    load_stage(0, 0); CP_COMMIT();
    load_stage(1, 1); CP_COMMIT();
    load_stage(2, 2); CP_COMMIT();

    const int NK = H / BK;   // 16
    for (int kt = 0; kt < NK; kt++) {
        CP_WAIT2();
        __syncthreads();
        if (kt + 3 < NK) load_stage(kt + 3, (kt + 3) & 3);
        CP_COMMIT();

        uint32_t stb = sb0 + (uint32_t)(kt & 3) * STG1B;
#pragma unroll
        for (int ks = 0; ks < 4; ks++) {
            uint32_t kx = ks * 32;                // XOR offset (bits 5-6)
            uint32_t a[2][4], f1[2][4], f3[2][4];
            ldsm4(a[0],  stb + (aOf[0]  ^ kx));
            ldsm4(a[1],  stb + (aOf[1]  ^ kx));
            ldsm4(f1[0], stb + (b1Of[0] ^ kx));
            ldsm4(f1[1], stb + (b1Of[1] ^ kx));
            ldsm4(f3[0], stb + (b3Of[0] ^ kx));
            ldsm4(f3[1], stb + (b3Of[1] ^ kx));
#pragma unroll
            for (int nt = 0; nt < 4; nt++) {
                int p = nt >> 1, s = (nt & 1) * 2;
#pragma unroll
                for (int mt = 0; mt < 2; mt++) {
                    mma16(acc1[mt][nt], a[mt], f1[p][s], f1[p][s + 1]);
                    mma16(acc3[mt][nt], a[mt], f3[p][s], f3[p][s + 1]);
                }
            }
        }
    }

    // epilogue: SwiGLU -> g_hh fp16
#pragma unroll
    for (int mt = 0; mt < 2; mt++) {
#pragma unroll
        for (int hf = 0; hf < 2; hf++) {
            int m = m0 + wM * 32 + mt * 16 + q + hf * 8;
            if (m >= count) continue;
            __half* hrow = g_hh + (size_t)(off + m) * F + n0 + wN * 32;
#pragma unroll
            for (int nt = 0; nt < 4; nt++) {
                float g0 = acc1[mt][nt][hf * 2 + 0];
                float g1 = acc1[mt][nt][hf * 2 + 1];
                float u0 = acc3[mt][nt][hf * 2 + 0];
                float u1 = acc3[mt][nt][hf * 2 + 1];
                float h0 = (g0 / (1.f + expf(-g0))) * u0;
                float h1 = (g1 / (1.f + expf(-g1))) * u1;
                *(__half2*)(hrow + nt * 8 + 2 * tq) = __floats2half2_rn(h0, h1);
            }
        }
    }
}

// ---------------------------------------------------------------------------
// 2. gemm2: y = c * (h @ W2^T), fp16 out
//    CTA 128x256, 512 thr, warps 4Mx4N (warp 32x64), BK=64.
//    Grid (x=expert, y=n-tile, z=m-tile).
// ---------------------------------------------------------------------------
__global__ __launch_bounds__(512, 1) void gemm2_tc() {
    int e     = blockIdx.x;
    int off   = e * T;
    int count = g_counts[e];
    int m0    = blockIdx.z * 128;
    if (m0 >= count) return;
    int n0 = blockIdx.y * 256;

    extern __shared__ __half smh[];

    int tid = threadIdx.x, wid = tid >> 5, lane = tid & 31;
    int q = lane >> 2, tq = lane & 3;
    int wM = wid & 3, wN = wid >> 2;        // 4 x 4 warps, warp 32x64

    const __half* w2e = g_w2h + ((size_t)e * H + n0) * F;
    int cm1 = count - 1;

    uint32_t sb0 = smem_u32(smh);
    int lrow = tid >> 2, lseg = tid & 3;
    uint32_t wd0 = SWB128((uint32_t)(lrow * 128 + lseg * 16));
    uint32_t wd1 = SWB128((uint32_t)(lrow * 128 + (lseg + 4) * 16));
    uint32_t we0 = SWB128((uint32_t)((128 + lrow) * 128 + lseg * 16));
    uint32_t we1 = SWB128((uint32_t)((128 + lrow) * 128 + (lseg + 4) * 16));
    int arow = off + min(m0 + lrow, cm1);

    uint32_t aOf[2], bOf[4];
#pragma unroll
    for (int mt = 0; mt < 2; mt++) aOf[mt] = a_off128(wM * 32 + mt * 16, lane);
#pragma unroll
    for (int p = 0; p < 4; p++) bOf[p] = 16384 + b_off128(wN * 64 + p * 16, lane);

    auto load_stage = [&](int kt, int buf) {
        uint32_t sb = sb0 + (uint32_t)buf * STG2B;
        int kf0 = kt * BK + lseg * 8;
        int kf1 = kf0 + 32;
        const __half* hrow = g_hh + (size_t)arow * F;
        cp_async16(sb + wd0, hrow + kf0);
        cp_async16(sb + wd1, hrow + kf1);
        cp_async16(sb + 16384 + wd0, w2e + (size_t)lrow         * F + kf0);
        cp_async16(sb + 16384 + wd1, w2e + (size_t)lrow         * F + kf1);
        cp_async16(sb + 16384 + we0, w2e + (size_t)(128 + lrow) * F + kf0);
        cp_async16(sb + 16384 + we1, w2e + (size_t)(128 + lrow) * F + kf1);
    };

    float acc[2][8][4] = {};

    load_stage(0, 0); CP_COMMIT();
    load_stage(1, 1); CP_COMMIT();
    load_stage(2, 2); CP_COMMIT();

    const int NK = F / BK;   // 8
    for (int kt = 0; kt < NK; kt++) {
        CP_WAIT2();
        __syncthreads();
        if (kt + 3 < NK) load_stage(kt + 3, (kt + 3) & 3);
        CP_COMMIT();

        uint32_t stb = sb0 + (uint32_t)(kt & 3) * STG2B;
#pragma unroll
        for (int ks = 0; ks < 4; ks++) {
            uint32_t kx = ks * 32;                // XOR offset
            uint32_t a[2][4], fb[4][4];
            ldsm4(a[0],  stb + (aOf[0] ^ kx));
            ldsm4(a[1],  stb + (aOf[1] ^ kx));
#pragma unroll
            for (int p = 0; p < 4; p++)
                ldsm4(fb[p], stb + (bOf[p] ^ kx));
#pragma unroll
            for (int nt = 0; nt < 8; nt++) {
                int p = nt >> 1, s = (nt & 1) * 2;
#pragma unroll
                for (int mt = 0; mt < 2; mt++)
                    mma16(acc[mt][nt], a[mt], fb[p][s], fb[p][s + 1]);
            }
        }
    }

    // epilogue: scale by combine weight, store g_yh fp16
#pragma unroll
    for (int mt = 0; mt < 2; mt++) {
#pragma unroll
        for (int hf = 0; hf < 2; hf++) {
            int m = m0 + wM * 32 + mt * 16 + q + hf * 8;
            if (m >= count) continue;
            float cw = g_slot_w[off + m];
            __half* yrow = g_yh + (size_t)(off + m) * H + n0 + wN * 64;
#pragma unroll
            for (int nt = 0; nt < 8; nt++) {
                float o0 = cw * acc[mt][nt][hf * 2 + 0];
                float o1 = cw * acc[mt][nt][hf * 2 + 1];
                *(__half2*)(yrow + nt * 8 + 2 * tq) = __floats2half2_rn(o0, o1);
            }
        }
    }
}

// ---------------------------------------------------------------------------
// 3. combine: out[t] = sum of token's K slot rows; re-zeroes g_counts.
//    Streaming stores on out (never re-read) keep L2 for y.
// ---------------------------------------------------------------------------
__global__ void combine_kernel(float* __restrict__ out) {
    int t = blockIdx.x;
    if (t == 0 && threadIdx.x < E) g_counts[threadIdx.x] = 0;
    const __half* y0 = g_yh + (size_t)g_token_slot[t * K + 0] * H;
    const __half* y1 = g_yh + (size_t)g_token_slot[t * K + 1] * H;
    const __half* y2 = g_yh + (size_t)g_token_slot[t * K + 2] * H;
    const __half* y3 = g_yh + (size_t)g_token_slot[t * K + 3] * H;
    float* orow = out + (size_t)t * H;
    for (int c = threadIdx.x * 4; c < H; c += blockDim.x * 4) {
        uint2 a = *(const uint2*)(y0 + c), b = *(const uint2*)(y1 + c);
        uint2 cc = *(const uint2*)(y2 + c), d = *(const uint2*)(y3 + c);
        const __half2* ah = (const __half2*)&a;
        const __half2* bh = (const __half2*)&b;
        const __half2* ch = (const __half2*)&cc;
        const __half2* dh = (const __half2*)&d;
        float4 v;
        v.x = __low2float(ah[0])  + __low2float(bh[0])  + __low2float(ch[0])  + __low2float(dh[0]);
        v.y = __high2float(ah[0]) + __high2float(bh[0]) + __high2float(ch[0]) + __high2float(dh[0]);
        v.z = __low2float(ah[1])  + __low2float(bh[1])  + __low2float(ch[1])  + __low2float(dh[1]);
        v.w = __high2float(ah[1]) + __high2float(bh[1]) + __high2float(ch[1]) + __high2float(dh[1]);
        __stcs((float4*)(orow + c), v);
    }
}

// ---------------------------------------------------------------------------
extern "C" void kernel_launch(void* const* d_in, const int* in_sizes, int n_in,
                              void* d_out, int out_size) {
    const float* x    = (const float*)d_in[0];
    const float* gw   = (const float*)d_in[1];
    const float* bias = (const float*)d_in[2];
    const float* w1   = (const float*)d_in[3];
    const float* w3   = (const float*)d_in[4];
    const float* w2   = (const float*)d_in[5];
    float* out = (float*)d_out;

    const int SM1 = 4 * STG1B;   // 196608 B
    const int SM2 = 4 * STG2B;   // 196608 B
    cudaFuncSetAttribute(gemm1_tc, cudaFuncAttributeMaxDynamicSharedMemorySize, SM1);
    cudaFuncSetAttribute(gemm2_tc, cudaFuncAttributeMaxDynamicSharedMemorySize, SM2);

    prep_router_kernel<<<RB + PB, 256>>>(x, gw, bias, (const float4*)w1,
                                         (const float4*)w3);

    // grid (x=expert[+1], y=n-tile, z=m-tile): expert-fastest dispatch
    gemm1_tc<<<dim3(E + 1, F / 128, T / 128), 512, SM1>>>((const float4*)w2);
    gemm2_tc<<<dim3(E, H / 256, T / 128), 512, SM2>>>();

    combine_kernel<<<T, 256>>>(out);
}

// round 17
// speedup vs baseline: 1.0094x; 1.0094x over previous
#include <cuda_runtime.h>
#include <cuda_fp16.h>
#include <cstdint>
#include <math.h>

#define T 4096
#define H 1024
#define F 512
#define E 16
#define K 4
#define S (T*K)
#define SP ((size_t)E * T)          // padded slot space (per-expert regions)

// ---------------- scratch (device globals; no runtime allocation) ----------
__device__ int    g_counts[E];      // zero-init at load; re-zeroed by combine
__device__ int    g_slot_token[SP];
__device__ float  g_slot_w[SP];
__device__ int    g_token_slot[S];
// fp16 (RN) operands / activations / outputs
__device__ __align__(256) __half g_xh [(size_t)T * H];
__device__ __align__(256) __half g_w1h[(size_t)E * F * H];
__device__ __align__(256) __half g_w3h[(size_t)E * F * H];
__device__ __align__(256) __half g_w2h[(size_t)E * H * F];
__device__ __align__(256) __half g_hh [SP * F];
__device__ __align__(256) __half g_yh [SP * H];

// ---------------- helpers ---------------------------------------------------
__device__ __forceinline__ void mma16(float* d, const uint32_t* a,
                                      uint32_t b0, uint32_t b1) {
    asm volatile(
        "mma.sync.aligned.m16n8k16.row.col.f32.f16.f16.f32 "
        "{%0,%1,%2,%3}, {%4,%5,%6,%7}, {%8,%9}, {%0,%1,%2,%3};"
        : "+f"(d[0]), "+f"(d[1]), "+f"(d[2]), "+f"(d[3])
        : "r"(a[0]), "r"(a[1]), "r"(a[2]), "r"(a[3]), "r"(b0), "r"(b1));
}
__device__ __forceinline__ void ldsm4(uint32_t* r, uint32_t addr) {
    asm volatile(
        "ldmatrix.sync.aligned.m8n8.x4.shared.b16 {%0,%1,%2,%3}, [%4];"
        : "=r"(r[0]), "=r"(r[1]), "=r"(r[2]), "=r"(r[3]) : "r"(addr));
}
__device__ __forceinline__ uint32_t smem_u32(const void* p) {
    uint32_t a;
    asm("{ .reg .u64 t; cvta.to.shared.u64 t, %1; cvt.u32.u64 %0, t; }"
        : "=r"(a) : "l"(p));
    return a;
}
__device__ __forceinline__ void cp_async16(uint32_t dst, const void* src) {
    asm volatile("cp.async.cg.shared.global [%0], [%1], 16;" :: "r"(dst), "l"(src));
}
#define CP_COMMIT() asm volatile("cp.async.commit_group;" ::: "memory")
#define CP_WAIT2()  asm volatile("cp.async.wait_group 2;" ::: "memory")

// 128B-row SW128 swizzle (Swizzle<3,4,3>): XOR row bits [0:3) into 16B-col
// bits [4:7). ks chunk offsets {0,32,64,96} -> addr(ks) == addr(0) ^ (ks*32).
#define SWB128(b) ((b) ^ (((((uint32_t)(b)) >> 7) & 7) << 4))

#define BK 64
#define STG1B 49152     // gemm1: x 16KB + w1 16KB + w3 16KB (128B rows)
#define STG2B 49152     // gemm2: h 16KB + w2 32KB

// ---------------------------------------------------------------------------
// fp32x8 -> fp16x8 (RN); streaming store (evict-first: arrays >> L2, caching
// them on write would only evict x / g_hh, which DO benefit from L2)
// ---------------------------------------------------------------------------
__device__ __forceinline__ uint4 cvt8(float4 f0, float4 f1) {
    __half2 h0 = __floats2half2_rn(f0.x, f0.y), h1 = __floats2half2_rn(f0.z, f0.w);
    __half2 h2 = __floats2half2_rn(f1.x, f1.y), h3 = __floats2half2_rn(f1.z, f1.w);
    uint4 o;
    o.x = *(uint32_t*)&h0; o.y = *(uint32_t*)&h1;
    o.z = *(uint32_t*)&h2; o.w = *(uint32_t*)&h3;
    return o;
}
__device__ __forceinline__ void conv8_cs(const float4* __restrict__ src,
                                         uint4* __restrict__ dst, size_t i) {
    __stcs(&dst[i], cvt8(src[2 * i], src[2 * i + 1]));
}

// ---------------------------------------------------------------------------
// 0. fused prep + router
//    blocks [0, RB): router (exact fp32, float4-vectorized) + fp16 x emit
//    blocks [RB, RB+PB): w1 & w3 conversion (interleaved, streaming stores)
// ---------------------------------------------------------------------------
#define RB 512
#define PB 1536

__global__ void prep_router_kernel(const float* __restrict__ x,
                                   const float* __restrict__ gw,
                                   const float* __restrict__ bias,
                                   const float4* __restrict__ w1,
                                   const float4* __restrict__ w3) {
    if (blockIdx.x >= RB) {
        size_t i0 = (size_t)(blockIdx.x - RB) * blockDim.x + threadIdx.x;
        size_t stride = (size_t)PB * blockDim.x;
        const size_t nw = (size_t)E * F * H / 8;
        for (size_t i = i0; i < nw; i += stride) {   // interleaved: 2x MLP
            conv8_cs(w1, (uint4*)g_w1h, i);
            conv8_cs(w3, (uint4*)g_w3h, i);
        }
        return;
    }
    // ---- router: one warp per token; float4 loads, coalesced fp16 stores ----
    int warp = (blockIdx.x * blockDim.x + threadIdx.x) >> 5;
    int lane = threadIdx.x & 31;
    if (warp >= T) return;

    const float4* xr4 = (const float4*)(x + (size_t)warp * H);
    __half2* xo2 = (__half2*)(g_xh + (size_t)warp * H);
    float acc[E];
#pragma unroll
    for (int e = 0; e < E; e++) acc[e] = 0.f;
#pragma unroll
    for (int it = 0; it < H / 128; it++) {       // 8 iters, 4 floats/lane
        int h4 = it * 32 + lane;
        float4 xv = xr4[h4];
        xo2[h4 * 2 + 0] = __floats2half2_rn(xv.x, xv.y);
        xo2[h4 * 2 + 1] = __floats2half2_rn(xv.z, xv.w);
#pragma unroll
        for (int e = 0; e < E; e++) {
            float4 g = __ldg((const float4*)(gw + e * H) + h4);
            acc[e] = fmaf(xv.x, g.x, fmaf(xv.y, g.y,
                     fmaf(xv.z, g.z, fmaf(xv.w, g.w, acc[e]))));
        }
    }
#pragma unroll
    for (int o = 16; o > 0; o >>= 1)
#pragma unroll
        for (int e = 0; e < E; e++)
            acc[e] += __shfl_xor_sync(0xffffffffu, acc[e], o);

    if (lane == 0) {
        float sc[E], sel[E];
#pragma unroll
        for (int e = 0; e < E; e++) {
            sc[e]  = 1.f / (1.f + expf(-acc[e]));
            sel[e] = sc[e] + bias[e];
        }
        bool used[E];
#pragma unroll
        for (int e = 0; e < E; e++) used[e] = false;
        float sum = 0.f;
        int   idx[K]; float w[K];
#pragma unroll
        for (int k = 0; k < K; k++) {
            float best = -1e30f; int bi = 0;
            for (int e = 0; e < E; e++)
                if (!used[e] && sel[e] > best) { best = sel[e]; bi = e; }
            used[bi] = true; idx[k] = bi; w[k] = sc[bi]; sum += sc[bi];
        }
        float inv = 1.f / sum;
#pragma unroll
        for (int k = 0; k < K; k++) {
            int e   = idx[k];
            int pos = e * T + atomicAdd(&g_counts[e], 1);
            g_slot_token[pos]        = warp;
            g_slot_w[pos]            = w[k] * inv;
            g_token_slot[warp*K + k] = pos;
        }
    }
}

// ---------------------------------------------------------------------------
// ldmatrix address offsets (region-relative, 128B rows; ks -> XOR ks*32)
// ---------------------------------------------------------------------------
__device__ __forceinline__ uint32_t a_off128(int r0, int lane) {
    int row = r0 + ((lane >> 3) & 1) * 8 + (lane & 7);
    return SWB128((uint32_t)(row * 128 + (lane >> 4) * 16));
}
__device__ __forceinline__ uint32_t b_off128(int c0, int lane) {
    int row = c0 + ((lane >> 4) << 3) + (lane & 7);
    return SWB128((uint32_t)(row * 128 + ((lane >> 3) & 1) * 16));
}

// ---------------------------------------------------------------------------
// 1. gemm1: h = silu(X@W1^T) * (X@W3^T)
//    CTA 128x128, 512 thr, warps 4Mx4N, BK=64, 4-stage cp.async.
//    Grid (x=expert[+1], y=n-tile, z=m-tile); x==E converts w2 (streaming).
// ---------------------------------------------------------------------------
__global__ __launch_bounds__(512, 1) void gemm1_tc(const float4* __restrict__ w2) {
    if (blockIdx.x == E) {
        size_t i0 = (size_t)(blockIdx.z * gridDim.y + blockIdx.y) * blockDim.x
                  + threadIdx.x;
        size_t stride = (size_t)gridDim.z * gridDim.y * blockDim.x;
        const size_t nw = (size_t)E * H * F / 8;
        for (size_t i = i0; i < nw; i += stride) conv8_cs(w2, (uint4*)g_w2h, i);
        return;
    }
    int e     = blockIdx.x;
    int off   = e * T;
    int count = g_counts[e];
    int m0    = blockIdx.z * 128;
    if (m0 >= count) return;
    int n0 = blockIdx.y * 128;

    extern __shared__ __half smh[];
    __shared__ int toks[128];

    int tid = threadIdx.x, wid = tid >> 5, lane = tid & 31;
    int q = lane >> 2, tq = lane & 3;
    int wM = wid & 3, wN = wid >> 2;        // 4 x 4 warps

    if (tid < 128) toks[tid] = g_slot_token[off + min(m0 + tid, count - 1)];
    __syncthreads();

    const __half* w1e = g_w1h + ((size_t)e * F + n0) * H;
    const __half* w3e = g_w3h + ((size_t)e * F + n0) * H;

    uint32_t sb0 = smem_u32(smh);
    int lrow = tid >> 2, lseg = tid & 3;     // 128 rows; segs {lseg, lseg+4}
    uint32_t wd0 = SWB128((uint32_t)(lrow * 128 + lseg * 16));
    uint32_t wd1 = SWB128((uint32_t)(lrow * 128 + (lseg + 4) * 16));

    uint32_t aOf[2], b1Of[2], b3Of[2];
#pragma unroll
    for (int mt = 0; mt < 2; mt++) aOf[mt] = a_off128(wM * 32 + mt * 16, lane);
#pragma unroll
    for (int p = 0; p < 2; p++) {
        b1Of[p] = 16384 + b_off128(wN * 32 + p * 16, lane);
        b3Of[p] = 32768 + b_off128(wN * 32 + p * 16, lane);
    }

    auto load_stage = [&](int kt, int buf) {
        uint32_t sb = sb0 + (uint32_t)buf * STG1B;
        int kf0 = kt * BK + lseg * 8;
        int kf1 = kf0 + 32;
        const __half* xrow = g_xh + (size_t)toks[lrow] * H;
        cp_async16(sb + wd0,         xrow + kf0);
        cp_async16(sb + wd1,         xrow + kf1);
        cp_async16(sb + 16384 + wd0, w1e + (size_t)lrow * H + kf0);
        cp_async16(sb + 16384 + wd1, w1e + (size_t)lrow * H + kf1);
        cp_async16(sb + 32768 + wd0, w3e + (size_t)lrow * H + kf0);
        cp_async16(sb + 32768 + wd1, w3e + (size_t)lrow * H + kf1);
    };

    float acc1[2][4][4] = {}, acc3[2][4][4] = {};

    load_stage(0, 0); CP_COMMIT();
    load_stage(1, 1); CP_COMMIT();
    load_stage(2, 2); CP_COMMIT();

    const int NK = H / BK;   // 16
    for (int kt = 0; kt < NK; kt++) {
        CP_WAIT2();
        __syncthreads();
        if (kt + 3 < NK) load_stage(kt + 3, (kt + 3) & 3);
        CP_COMMIT();

        uint32_t stb = sb0 + (uint32_t)(kt & 3) * STG1B;
#pragma unroll
        for (int ks = 0; ks < 4; ks++) {
            uint32_t kx = ks * 32;                // XOR offset (bits 5-6)
            uint32_t a[2][4], f1[2][4], f3[2][4];
            ldsm4(a[0],  stb + (aOf[0]  ^ kx));
            ldsm4(a[1],  stb + (aOf[1]  ^ kx));
            ldsm4(f1[0], stb + (b1Of[0] ^ kx));
            ldsm4(f1[1], stb + (b1Of[1] ^ kx));
            ldsm4(f3[0], stb + (b3Of[0] ^ kx));
            ldsm4(f3[1], stb + (b3Of[1] ^ kx));
#pragma unroll
            for (int nt = 0; nt < 4; nt++) {
                int p = nt >> 1, s = (nt & 1) * 2;
#pragma unroll
                for (int mt = 0; mt < 2; mt++) {
                    mma16(acc1[mt][nt], a[mt], f1[p][s], f1[p][s + 1]);
                    mma16(acc3[mt][nt], a[mt], f3[p][s], f3[p][s + 1]);
                }
            }
        }
    }

    // epilogue: SwiGLU -> g_hh fp16
#pragma unroll
    for (int mt = 0; mt < 2; mt++) {
#pragma unroll
        for (int hf = 0; hf < 2; hf++) {
            int m = m0 + wM * 32 + mt * 16 + q + hf * 8;
            if (m >= count) continue;
            __half* hrow = g_hh + (size_t)(off + m) * F + n0 + wN * 32;
#pragma unroll
            for (int nt = 0; nt < 4; nt++) {
                float g0 = acc1[mt][nt][hf * 2 + 0];
                float g1 = acc1[mt][nt][hf * 2 + 1];
                float u0 = acc3[mt][nt][hf * 2 + 0];
                float u1 = acc3[mt][nt][hf * 2 + 1];
                float h0 = (g0 / (1.f + expf(-g0))) * u0;
                float h1 = (g1 / (1.f + expf(-g1))) * u1;
                *(__half2*)(hrow + nt * 8 + 2 * tq) = __floats2half2_rn(h0, h1);
            }
        }
    }
}

// ---------------------------------------------------------------------------
// 2. gemm2: y = c * (h @ W2^T), fp16 out
//    CTA 128x256, 512 thr, warps 4Mx4N (warp 32x64), BK=64.
//    Grid (x=expert, y=n-tile, z=m-tile).
// ---------------------------------------------------------------------------
__global__ __launch_bounds__(512, 1) void gemm2_tc() {
    int e     = blockIdx.x;
    int off   = e * T;
    int count = g_counts[e];
    int m0    = blockIdx.z * 128;
    if (m0 >= count) return;
    int n0 = blockIdx.y * 256;

    extern __shared__ __half smh[];

    int tid = threadIdx.x, wid = tid >> 5, lane = tid & 31;
    int q = lane >> 2, tq = lane & 3;
    int wM = wid & 3, wN = wid >> 2;        // 4 x 4 warps, warp 32x64

    const __half* w2e = g_w2h + ((size_t)e * H + n0) * F;
    int cm1 = count - 1;

    uint32_t sb0 = smem_u32(smh);
    int lrow = tid >> 2, lseg = tid & 3;
    uint32_t wd0 = SWB128((uint32_t)(lrow * 128 + lseg * 16));
    uint32_t wd1 = SWB128((uint32_t)(lrow * 128 + (lseg + 4) * 16));
    uint32_t we0 = SWB128((uint32_t)((128 + lrow) * 128 + lseg * 16));
    uint32_t we1 = SWB128((uint32_t)((128 + lrow) * 128 + (lseg + 4) * 16));
    int arow = off + min(m0 + lrow, cm1);

    uint32_t aOf[2], bOf[4];
#pragma unroll
    for (int mt = 0; mt < 2; mt++) aOf[mt] = a_off128(wM * 32 + mt * 16, lane);
#pragma unroll
    for (int p = 0; p < 4; p++) bOf[p] = 16384 + b_off128(wN * 64 + p * 16, lane);

    auto load_stage = [&](int kt, int buf) {
        uint32_t sb = sb0 + (uint32_t)buf * STG2B;
        int kf0 = kt * BK + lseg * 8;
        int kf1 = kf0 + 32;
        const __half* hrow = g_hh + (size_t)arow * F;
        cp_async16(sb + wd0, hrow + kf0);
        cp_async16(sb + wd1, hrow + kf1);
        cp_async16(sb + 16384 + wd0, w2e + (size_t)lrow         * F + kf0);
        cp_async16(sb + 16384 + wd1, w2e + (size_t)lrow         * F + kf1);
        cp_async16(sb + 16384 + we0, w2e + (size_t)(128 + lrow) * F + kf0);
        cp_async16(sb + 16384 + we1, w2e + (size_t)(128 + lrow) * F + kf1);
    };

    float acc[2][8][4] = {};

    load_stage(0, 0); CP_COMMIT();
    load_stage(1, 1); CP_COMMIT();
    load_stage(2, 2); CP_COMMIT();

    const int NK = F / BK;   // 8
    for (int kt = 0; kt < NK; kt++) {
        CP_WAIT2();
        __syncthreads();
        if (kt + 3 < NK) load_stage(kt + 3, (kt + 3) & 3);
        CP_COMMIT();

        uint32_t stb = sb0 + (uint32_t)(kt & 3) * STG2B;
#pragma unroll
        for (int ks = 0; ks < 4; ks++) {
            uint32_t kx = ks * 32;                // XOR offset
            uint32_t a[2][4], fb[4][4];
            ldsm4(a[0],  stb + (aOf[0] ^ kx));
            ldsm4(a[1],  stb + (aOf[1] ^ kx));
#pragma unroll
            for (int p = 0; p < 4; p++)
                ldsm4(fb[p], stb + (bOf[p] ^ kx));
#pragma unroll
            for (int nt = 0; nt < 8; nt++) {
                int p = nt >> 1, s = (nt & 1) * 2;
#pragma unroll
                for (int mt = 0; mt < 2; mt++)
                    mma16(acc[mt][nt], a[mt], fb[p][s], fb[p][s + 1]);
            }
        }
    }

    // epilogue: scale by combine weight, store g_yh fp16
#pragma unroll
    for (int mt = 0; mt < 2; mt++) {
#pragma unroll
        for (int hf = 0; hf < 2; hf++) {
            int m = m0 + wM * 32 + mt * 16 + q + hf * 8;
            if (m >= count) continue;
            float cw = g_slot_w[off + m];
            __half* yrow = g_yh + (size_t)(off + m) * H + n0 + wN * 64;
#pragma unroll
            for (int nt = 0; nt < 8; nt++) {
                float o0 = cw * acc[mt][nt][hf * 2 + 0];
                float o1 = cw * acc[mt][nt][hf * 2 + 1];
                *(__half2*)(yrow + nt * 8 + 2 * tq) = __floats2half2_rn(o0, o1);
            }
        }
    }
}

// ---------------------------------------------------------------------------
// 3. combine: out[t] = sum of token's K slot rows; re-zeroes g_counts.
//    Streaming stores on out (never re-read) keep L2 for y.
// ---------------------------------------------------------------------------
__global__ void combine_kernel(float* __restrict__ out) {
    int t = blockIdx.x;
    if (t == 0 && threadIdx.x < E) g_counts[threadIdx.x] = 0;
    const __half* y0 = g_yh + (size_t)g_token_slot[t * K + 0] * H;
    const __half* y1 = g_yh + (size_t)g_token_slot[t * K + 1] * H;
    const __half* y2 = g_yh + (size_t)g_token_slot[t * K + 2] * H;
    const __half* y3 = g_yh + (size_t)g_token_slot[t * K + 3] * H;
    float* orow = out + (size_t)t * H;
    for (int c = threadIdx.x * 4; c < H; c += blockDim.x * 4) {
        uint2 a = *(const uint2*)(y0 + c), b = *(const uint2*)(y1 + c);
        uint2 cc = *(const uint2*)(y2 + c), d = *(const uint2*)(y3 + c);
        const __half2* ah = (const __half2*)&a;
        const __half2* bh = (const __half2*)&b;
        const __half2* ch = (const __half2*)&cc;
        const __half2* dh = (const __half2*)&d;
        float4 v;
        v.x = __low2float(ah[0])  + __low2float(bh[0])  + __low2float(ch[0])  + __low2float(dh[0]);
        v.y = __high2float(ah[0]) + __high2float(bh[0]) + __high2float(ch[0]) + __high2float(dh[0]);
        v.z = __low2float(ah[1])  + __low2float(bh[1])  + __low2float(ch[1])  + __low2float(dh[1]);
        v.w = __high2float(ah[1]) + __high2float(bh[1]) + __high2float(ch[1]) + __high2float(dh[1]);
        __stcs((float4*)(orow + c), v);
    }
}

// ---------------------------------------------------------------------------
extern "C" void kernel_launch(void* const* d_in, const int* in_sizes, int n_in,
                              void* d_out, int out_size) {
    const float* x    = (const float*)d_in[0];
    const float* gw   = (const float*)d_in[1];
    const float* bias = (const float*)d_in[2];
    const float* w1   = (const float*)d_in[3];
    const float* w3   = (const float*)d_in[4];
    const float* w2   = (const float*)d_in[5];
    float* out = (float*)d_out;

    const int SM1 = 4 * STG1B;   // 196608 B
    const int SM2 = 4 * STG2B;   // 196608 B
    cudaFuncSetAttribute(gemm1_tc, cudaFuncAttributeMaxDynamicSharedMemorySize, SM1);
    cudaFuncSetAttribute(gemm2_tc, cudaFuncAttributeMaxDynamicSharedMemorySize, SM2);

    prep_router_kernel<<<RB + PB, 256>>>(x, gw, bias, (const float4*)w1,
                                         (const float4*)w3);

    // grid (x=expert[+1], y=n-tile, z=m-tile): expert-fastest dispatch
    gemm1_tc<<<dim3(E + 1, F / 128, T / 128), 512, SM1>>>((const float4*)w2);
    gemm2_tc<<<dim3(E, H / 256, T / 128), 512, SM2>>>();

    combine_kernel<<<T, 256>>>(out);
}